// round 5
// baseline (speedup 1.0000x reference)
#include <cuda_runtime.h>
#include <cuda_bf16.h>
#include <math.h>
#include <stdint.h>

#define H 16
#define HS 128
#define ROT 32
#define S_LEN 2048
#define B_SZ 2
#define D_MODEL 2048
#define N_QKV 6144
#define M_ROWS 4096
#define SCALE 0.08838834764831845f  // 1/sqrt(128)

// ---------------- scratch (__device__ globals) ------------------------------
__device__ uint32_t g_Ahi[(size_t)M_ROWS * D_MODEL / 2];
__device__ uint32_t g_Alo[(size_t)M_ROWS * D_MODEL / 2];
__device__ __nv_bfloat16 g_Whi[(size_t)N_QKV * D_MODEL];
__device__ __nv_bfloat16 g_Wlo[(size_t)N_QKV * D_MODEL];
__device__ __nv_bfloat16 g_DHhi[(size_t)D_MODEL * D_MODEL];
__device__ __nv_bfloat16 g_DHlo[(size_t)D_MODEL * D_MODEL];
__device__ uint32_t g_Phi[(size_t)M_ROWS * D_MODEL / 2];
__device__ uint32_t g_Plo[(size_t)M_ROWS * D_MODEL / 2];
__device__ uint32_t g_Qh[(size_t)B_SZ * H * S_LEN * (HS / 2)];
__device__ uint32_t g_Ql[(size_t)B_SZ * H * S_LEN * (HS / 2)];
__device__ uint32_t g_Kh[(size_t)B_SZ * H * S_LEN * (HS / 2)];
__device__ uint32_t g_Kl[(size_t)B_SZ * H * S_LEN * (HS / 2)];
__device__ uint32_t g_Vh[(size_t)B_SZ * H * HS * (S_LEN / 2)];
__device__ uint32_t g_Vl[(size_t)B_SZ * H * HS * (S_LEN / 2)];
__device__ float g_cosT[S_LEN * 16];
__device__ float g_sinT[S_LEN * 16];

// ---------------- PTX helpers ------------------------------------------------
__device__ __forceinline__ uint32_t smem_u32(const void* p) {
    uint32_t a;
    asm("{ .reg .u64 t; cvta.to.shared.u64 t, %1; cvt.u32.u64 %0, t; }"
        : "=r"(a) : "l"(p));
    return a;
}
__device__ __forceinline__ void cp16(uint32_t dst, const void* src) {
    asm volatile("cp.async.cg.shared.global [%0], [%1], 16;" :: "r"(dst), "l"(src));
}
__device__ __forceinline__ void cp_commit() {
    asm volatile("cp.async.commit_group;" ::: "memory");
}
template <int N>
__device__ __forceinline__ void cp_wait() {
    asm volatile("cp.async.wait_group %0;" :: "n"(N) : "memory");
}
__device__ __forceinline__ void ldm4(uint32_t* d, uint32_t addr) {
    asm volatile("ldmatrix.sync.aligned.m8n8.x4.shared.b16 {%0,%1,%2,%3}, [%4];"
                 : "=r"(d[0]), "=r"(d[1]), "=r"(d[2]), "=r"(d[3]) : "r"(addr));
}
__device__ __forceinline__ void mma16816(float* c, const uint32_t* a, const uint32_t* b)
{
    asm volatile(
        "mma.sync.aligned.m16n8k16.row.col.f32.bf16.bf16.f32 "
        "{%0,%1,%2,%3}, {%4,%5,%6,%7}, {%8,%9}, {%0,%1,%2,%3};"
        : "+f"(c[0]), "+f"(c[1]), "+f"(c[2]), "+f"(c[3])
        : "r"(a[0]), "r"(a[1]), "r"(a[2]), "r"(a[3]), "r"(b[0]), "r"(b[1]));
}
__device__ __forceinline__ void split2(float x, float y, uint32_t& hi, uint32_t& lo)
{
    __nv_bfloat162 h = __floats2bfloat162_rn(x, y);
    float rx = x - __bfloat162float(h.x);
    float ry = y - __bfloat162float(h.y);
    __nv_bfloat162 l = __floats2bfloat162_rn(rx, ry);
    hi = *reinterpret_cast<uint32_t*>(&h);
    lo = *reinterpret_cast<uint32_t*>(&l);
}

// ---------------- small prep kernels -----------------------------------------
__global__ void split_convert(const float* __restrict__ x,
                              uint32_t* __restrict__ hi,
                              uint32_t* __restrict__ lo, int n4)
{
    int i = blockIdx.x * blockDim.x + threadIdx.x;
    if (i >= n4) return;
    float4 v = ((const float4*)x)[i];
    uint32_t h0, l0, h1, l1;
    split2(v.x, v.y, h0, l0);
    split2(v.z, v.w, h1, l1);
    hi[i * 2]     = h0;
    hi[i * 2 + 1] = h1;
    lo[i * 2]     = l0;
    lo[i * 2 + 1] = l1;
}

__global__ void transpose_split(const float* __restrict__ W,
                                __nv_bfloat16* __restrict__ Thi,
                                __nv_bfloat16* __restrict__ Tlo, int K, int N)
{
    __shared__ float t[32][33];
    int n0 = blockIdx.x * 32, k0 = blockIdx.y * 32;
    int tx = threadIdx.x, ty = threadIdx.y;
#pragma unroll
    for (int i = 0; i < 32; i += 8)
        t[ty + i][tx] = W[(size_t)(k0 + ty + i) * N + n0 + tx];
    __syncthreads();
#pragma unroll
    for (int i = 0; i < 32; i += 8) {
        float x = t[tx][ty + i];
        __nv_bfloat16 h = __float2bfloat16_rn(x);
        __nv_bfloat16 l = __float2bfloat16_rn(x - __bfloat162float(h));
        size_t o = (size_t)(n0 + ty + i) * K + k0 + tx;
        Thi[o] = h;
        Tlo[o] = l;
    }
}

__global__ void rope_table()
{
    int idx = blockIdx.x * blockDim.x + threadIdx.x;
    if (idx >= S_LEN * 16) return;
    int p = idx >> 4, i = idx & 15;
    float inv = (float)pow(10000.0, -(double)(2 * i) / (double)ROT);
    float a = (float)p * inv;
    float s, c;
    sincosf(a, &s, &c);
    g_cosT[idx] = c;
    g_sinT[idx] = s;
}

// ---------------- GEMM: cp.async 4-stage + ldmatrix --------------------------
// C[M,N] = A @ B^T + bias. Block 128x128, 8 warps (2x4), warp 64x32, KC=32.
// Stage 32KB: Ah@0, Al@8K, Bh@16K, Bl@24K. Row = 64B = 4 chunks of 16B.
// mode 0: plain epilogue (bias + fp32 C)
// mode 1: fused QKV epilogue (stage in smem; RoPE+scale+split for q/k; V transpose+split)
#define GKC 32
#define GSTG 32768
#define GEMM_SMEM (4 * GSTG)
#define TSTR 132

__device__ __forceinline__ uint32_t gswz(int row, int chunk) {
    return (uint32_t)(row * 64 + ((chunk ^ ((row >> 1) & 3)) << 4));
}

__global__ __launch_bounds__(256, 1) void gemm_mma(
    const uint32_t* __restrict__ Ah, const uint32_t* __restrict__ Al,
    const uint32_t* __restrict__ Bh, const uint32_t* __restrict__ Bl,
    const float* __restrict__ bias, float* __restrict__ C,
    const int* __restrict__ pos, int mode,
    int M, int N, int K)
{
    extern __shared__ uint32_t smg[];
    const uint32_t sb = smem_u32(smg);
    const int tid = threadIdx.x;
    const int w = tid >> 5, lane = tid & 31;
    const int g = lane >> 2, tig = lane & 3;
    const int r8 = lane & 7, mi = lane >> 3;
    const int wm = (w >> 2) * 64, wn = (w & 3) * 32;
    const int m0 = blockIdx.y * 128, n0 = blockIdx.x * 128;
    const int K2 = K >> 1;
    const int NCH = K / GKC;

    float acc[4][4][4];
#pragma unroll
    for (int i = 0; i < 4; i++)
#pragma unroll
        for (int j = 0; j < 4; j++)
#pragma unroll
            for (int k = 0; k < 4; k++) acc[i][j][k] = 0.0f;

    auto issue = [&](int c) {
        uint32_t st = sb + (c & 3) * GSTG;
        int kw = c * 16;
#pragma unroll
        for (int i = 0; i < 8; i++) {
            int idx = tid + i * 256;
            int arr = idx >> 9, rem = idx & 511;
            int row = rem >> 2, ch = rem & 3;
            const uint32_t* gp;
            if (arr == 0)      gp = Ah + (size_t)(m0 + row) * K2 + kw + ch * 4;
            else if (arr == 1) gp = Al + (size_t)(m0 + row) * K2 + kw + ch * 4;
            else if (arr == 2) gp = Bh + (size_t)(n0 + row) * K2 + kw + ch * 4;
            else               gp = Bl + (size_t)(n0 + row) * K2 + kw + ch * 4;
            cp16(st + arr * 8192 + gswz(row, ch), gp);
        }
        cp_commit();
    };

    issue(0); issue(1); issue(2);

    for (int c = 0; c < NCH; c++) {
        if (c + 3 < NCH) { issue(c + 3); cp_wait<3>(); }
        else             { cp_wait<0>(); }
        __syncthreads();
        uint32_t st = sb + (c & 3) * GSTG;

#pragma unroll
        for (int ks = 0; ks < 2; ks++) {
            uint32_t ahf[4][4], alf[4][4], bhf[4][2], blf[4][2];
#pragma unroll
            for (int mt = 0; mt < 4; mt++) {
                int row = wm + 16 * mt + ((mi & 1) << 3) + r8;
                int ch = 2 * ks + (mi >> 1);
                uint32_t sw = gswz(row, ch);
                ldm4(ahf[mt], st + sw);
                ldm4(alf[mt], st + 8192 + sw);
            }
#pragma unroll
            for (int j = 0; j < 2; j++) {
                int row = wn + 16 * j + ((mi >> 1) << 3) + r8;
                int ch = 2 * ks + (mi & 1);
                uint32_t sw = gswz(row, ch);
                uint32_t t4[4];
                ldm4(t4, st + 16384 + sw);
                bhf[2 * j][0] = t4[0]; bhf[2 * j][1] = t4[1];
                bhf[2 * j + 1][0] = t4[2]; bhf[2 * j + 1][1] = t4[3];
                ldm4(t4, st + 24576 + sw);
                blf[2 * j][0] = t4[0]; blf[2 * j][1] = t4[1];
                blf[2 * j + 1][0] = t4[2]; blf[2 * j + 1][1] = t4[3];
            }
#pragma unroll
            for (int mt = 0; mt < 4; mt++)
#pragma unroll
                for (int nt = 0; nt < 4; nt++) {
                    mma16816(acc[mt][nt], ahf[mt], bhf[nt]);
                    mma16816(acc[mt][nt], ahf[mt], blf[nt]);
                    mma16816(acc[mt][nt], alf[mt], bhf[nt]);
                }
        }
        __syncthreads();
    }

    if (mode == 0) {
        // ---- plain epilogue: bias + fp32 store ----
#pragma unroll
        for (int mt = 0; mt < 4; mt++)
#pragma unroll
            for (int nt = 0; nt < 4; nt++) {
                int row = m0 + wm + 16 * mt + g;
                int col = n0 + wn + 8 * nt + 2 * tig;
                float2 bv = *(const float2*)(bias + col);
                float2 o0 = make_float2(acc[mt][nt][0] + bv.x, acc[mt][nt][1] + bv.y);
                float2 o1 = make_float2(acc[mt][nt][2] + bv.x, acc[mt][nt][3] + bv.y);
                *(float2*)&C[(size_t)row * N + col]       = o0;
                *(float2*)&C[(size_t)(row + 8) * N + col] = o1;
            }
    } else {
        // ---- fused QKV epilogue: stage tile (with bias) in smem ----
        float* ts = (float*)smg;
#pragma unroll
        for (int mt = 0; mt < 4; mt++)
#pragma unroll
            for (int nt = 0; nt < 4; nt++) {
                int row = wm + 16 * mt + g;
                int col = wn + 8 * nt + 2 * tig;
                float2 bv = *(const float2*)(bias + n0 + col);
                *(float2*)&ts[row * TSTR + col] =
                    make_float2(acc[mt][nt][0] + bv.x, acc[mt][nt][1] + bv.y);
                *(float2*)&ts[(row + 8) * TSTR + col] =
                    make_float2(acc[mt][nt][2] + bv.x, acc[mt][nt][3] + bv.y);
            }
        __syncthreads();

        const int btype = (n0 >> 7) % 3;       // 0=q, 1=k, 2=v
        const int hd = n0 / 384;
        const int b = m0 >> 11;
        const int s0 = m0 & 2047;
        const int bh = b * H + hd;

        if (btype < 2) {
            uint32_t* dsth = btype == 0 ? g_Qh : g_Kh;
            uint32_t* dstl = btype == 0 ? g_Ql : g_Kl;
            const float qs = btype == 0 ? SCALE : 1.0f;
#pragma unroll
            for (int it = 0; it < 32; it++) {
                int idx = tid + it * 256;
                int r = idx >> 6, j = idx & 63;
                const float* tr = ts + r * TSTR;
                int d0 = 2 * j;
                float x0, x1;
                if (j < 8) {
                    int p = pos[m0 + r];
                    const float* ct = g_cosT + p * 16;
                    const float* st = g_sinT + p * 16;
                    x0 = tr[d0] * ct[d0] - tr[d0 + 16] * st[d0];
                    x1 = tr[d0 + 1] * ct[d0 + 1] - tr[d0 + 17] * st[d0 + 1];
                } else if (j < 16) {
                    int p = pos[m0 + r];
                    int i0 = d0 - 16;
                    const float* ct = g_cosT + p * 16;
                    const float* st = g_sinT + p * 16;
                    x0 = tr[d0] * ct[i0] + tr[i0] * st[i0];
                    x1 = tr[d0 + 1] * ct[i0 + 1] + tr[i0 + 1] * st[i0 + 1];
                } else {
                    x0 = tr[d0];
                    x1 = tr[d0 + 1];
                }
                uint32_t hi, lo;
                split2(x0 * qs, x1 * qs, hi, lo);
                size_t oi = ((size_t)bh * S_LEN + s0 + r) * 64 + j;
                dsth[oi] = hi;
                dstl[oi] = lo;
            }
        } else {
            // V: transposed write into [bh][d][S/2] pair layout
#pragma unroll
            for (int it = 0; it < 32; it++) {
                int idx = tid + it * 256;
                int d = idx >> 6, j = idx & 63;
                float v0 = ts[(2 * j) * TSTR + d];
                float v1 = ts[(2 * j + 1) * TSTR + d];
                uint32_t hi, lo;
                split2(v0, v1, hi, lo);
                size_t oi = (size_t)bh * HS * (S_LEN / 2)
                          + (size_t)d * (S_LEN / 2) + (s0 >> 1) + j;
                g_Vh[oi] = hi;
                g_Vl[oi] = lo;
            }
        }
    }
}

// ---------------- flash attention: cp.async 2-stage + ldmatrix ---------------
// Block: BQ=128, 256 threads (8 warps x 16 rows). BK=64.
// Stage 64KB: Kh@0, Kl@16K, Vh@32K, Vl@48K.
#define FSTG 65536
#define FA_SMEM (2 * FSTG)

__device__ __forceinline__ uint32_t kswz(int row, int chunk) {
    return (uint32_t)(row * 256 + ((chunk ^ (row & 7)) << 4));
}
__device__ __forceinline__ uint32_t vswz(int row, int chunk) {
    return (uint32_t)(row * 128 + ((chunk ^ (row & 7)) << 4));
}

__global__ __launch_bounds__(256, 1) void flash_mma()
{
    extern __shared__ uint32_t smf[];
    const uint32_t sb = smem_u32(smf);

    const int qt = blockIdx.x, h = blockIdx.y, b = blockIdx.z;
    const int tid = threadIdx.x;
    const int w = tid >> 5, lane = tid & 31;
    const int g = lane >> 2, tig = lane & 3;
    const int r8 = lane & 7, mi = lane >> 3;
    const int bh = b * H + h;

    // ---- hoist Q fragments (registers) ----
    const size_t qrow = (size_t)bh * S_LEN + qt * 128 + w * 16;
    const uint32_t* q0h = g_Qh + (qrow + g) * 64;
    const uint32_t* q8h = q0h + 8 * 64;
    const uint32_t* q0l = g_Ql + (qrow + g) * 64;
    const uint32_t* q8l = q0l + 8 * 64;
    uint32_t qh[8][4], ql[8][4];
#pragma unroll
    for (int ds = 0; ds < 8; ds++) {
        qh[ds][0] = q0h[ds * 8 + tig];
        qh[ds][1] = q8h[ds * 8 + tig];
        qh[ds][2] = q0h[ds * 8 + 4 + tig];
        qh[ds][3] = q8h[ds * 8 + 4 + tig];
        ql[ds][0] = q0l[ds * 8 + tig];
        ql[ds][1] = q8l[ds * 8 + tig];
        ql[ds][2] = q0l[ds * 8 + 4 + tig];
        ql[ds][3] = q8l[ds * 8 + 4 + tig];
    }

    auto issueKV = [&](int kt) {
        uint32_t st = sb + (kt & 1) * FSTG;
        const size_t kbase = ((size_t)bh * S_LEN + kt * 64) * 64;
        const size_t vbase = (size_t)bh * HS * (S_LEN / 2) + kt * 32;
#pragma unroll
        for (int i = 0; i < 8; i++) {
            int idx = tid + i * 256;
            int arr = idx >> 10, rem = idx & 1023;
            int row = rem >> 4, ch = rem & 15;
            const uint32_t* src = (arr ? g_Kl : g_Kh) + kbase + row * 64 + ch * 4;
            cp16(st + arr * 16384 + kswz(row, ch), src);
        }
#pragma unroll
        for (int i = 0; i < 8; i++) {
            int idx = tid + i * 256;
            int arr = idx >> 10, rem = idx & 1023;
            int row = rem >> 3, ch = rem & 7;
            const uint32_t* src = (arr ? g_Vl : g_Vh) + vbase
                                  + (size_t)row * (S_LEN / 2) + ch * 4;
            cp16(st + 32768 + arr * 16384 + vswz(row, ch), src);
        }
        cp_commit();
    };

    float o[16][4];
#pragma unroll
    for (int i = 0; i < 16; i++)
#pragma unroll
        for (int k = 0; k < 4; k++) o[i][k] = 0.0f;
    float m0 = -1e30f, m1 = -1e30f, l0 = 0.0f, l1 = 0.0f;

    issueKV(0);

    for (int kt = 0; kt < S_LEN / 64; kt++) {
        if (kt + 1 < S_LEN / 64) { issueKV(kt + 1); cp_wait<1>(); }
        else                     { cp_wait<0>(); }
        __syncthreads();
        uint32_t st = sb + (kt & 1) * FSTG;

        // ---- S = Q @ K^T ----
        float sc[8][4];
#pragma unroll
        for (int i = 0; i < 8; i++)
#pragma unroll
            for (int k = 0; k < 4; k++) sc[i][k] = 0.0f;

#pragma unroll
        for (int ds = 0; ds < 8; ds++) {
#pragma unroll
            for (int j = 0; j < 4; j++) {
                int row = 16 * j + ((mi >> 1) << 3) + r8;
                int ch = 2 * ds + (mi & 1);
                uint32_t sw = kswz(row, ch);
                uint32_t kh4[4], kl4[4];
                ldm4(kh4, st + sw);
                ldm4(kl4, st + 16384 + sw);
                mma16816(sc[2 * j],     qh[ds], kh4);
                mma16816(sc[2 * j],     qh[ds], kl4);
                mma16816(sc[2 * j],     ql[ds], kh4);
                mma16816(sc[2 * j + 1], qh[ds], kh4 + 2);
                mma16816(sc[2 * j + 1], qh[ds], kl4 + 2);
                mma16816(sc[2 * j + 1], ql[ds], kh4 + 2);
            }
        }

        // ---- online softmax ----
        float mx0 = -1e30f, mx1 = -1e30f;
#pragma unroll
        for (int nt = 0; nt < 8; nt++) {
            mx0 = fmaxf(mx0, fmaxf(sc[nt][0], sc[nt][1]));
            mx1 = fmaxf(mx1, fmaxf(sc[nt][2], sc[nt][3]));
        }
        mx0 = fmaxf(mx0, __shfl_xor_sync(0xffffffffu, mx0, 1));
        mx0 = fmaxf(mx0, __shfl_xor_sync(0xffffffffu, mx0, 2));
        mx1 = fmaxf(mx1, __shfl_xor_sync(0xffffffffu, mx1, 1));
        mx1 = fmaxf(mx1, __shfl_xor_sync(0xffffffffu, mx1, 2));

        float mn0 = fmaxf(m0, mx0);
        float mn1 = fmaxf(m1, mx1);
        float a0 = __expf(m0 - mn0);
        float a1 = __expf(m1 - mn1);
        m0 = mn0;
        m1 = mn1;
        float add0 = 0.0f, add1 = 0.0f;
#pragma unroll
        for (int nt = 0; nt < 8; nt++) {
            sc[nt][0] = __expf(sc[nt][0] - mn0);
            sc[nt][1] = __expf(sc[nt][1] - mn0);
            sc[nt][2] = __expf(sc[nt][2] - mn1);
            sc[nt][3] = __expf(sc[nt][3] - mn1);
            add0 += sc[nt][0] + sc[nt][1];
            add1 += sc[nt][2] + sc[nt][3];
        }
        l0 = l0 * a0 + add0;
        l1 = l1 * a1 + add1;
#pragma unroll
        for (int nt = 0; nt < 16; nt++) {
            o[nt][0] *= a0;
            o[nt][1] *= a0;
            o[nt][2] *= a1;
            o[nt][3] *= a1;
        }

        // ---- O += P @ V ----
#pragma unroll
        for (int kk = 0; kk < 4; kk++) {
            uint32_t ph[4], pl[4];
            split2(sc[2 * kk][0],     sc[2 * kk][1],     ph[0], pl[0]);
            split2(sc[2 * kk][2],     sc[2 * kk][3],     ph[1], pl[1]);
            split2(sc[2 * kk + 1][0], sc[2 * kk + 1][1], ph[2], pl[2]);
            split2(sc[2 * kk + 1][2], sc[2 * kk + 1][3], ph[3], pl[3]);
#pragma unroll
            for (int j = 0; j < 8; j++) {
                int row = 16 * j + ((mi >> 1) << 3) + r8;
                int ch = 2 * kk + (mi & 1);
                uint32_t sw = vswz(row, ch);
                uint32_t vh4[4], vl4[4];
                ldm4(vh4, st + 32768 + sw);
                ldm4(vl4, st + 49152 + sw);
                mma16816(o[2 * j],     ph, vh4);
                mma16816(o[2 * j],     ph, vl4);
                mma16816(o[2 * j],     pl, vh4);
                mma16816(o[2 * j + 1], ph, vh4 + 2);
                mma16816(o[2 * j + 1], ph, vl4 + 2);
                mma16816(o[2 * j + 1], pl, vh4 + 2);
            }
        }
        __syncthreads();
    }

    // ---- normalize, split, store directly to g_Phi/g_Plo ----
    l0 += __shfl_xor_sync(0xffffffffu, l0, 1);
    l0 += __shfl_xor_sync(0xffffffffu, l0, 2);
    l1 += __shfl_xor_sync(0xffffffffu, l1, 1);
    l1 += __shfl_xor_sync(0xffffffffu, l1, 2);
    float inv0 = 1.0f / l0;
    float inv1 = 1.0f / l1;

    size_t row0 = (size_t)(b * S_LEN + qt * 128 + w * 16 + g);
#pragma unroll
    for (int nt = 0; nt < 16; nt++) {
        size_t wd = h * 64 + nt * 4 + tig;
        uint32_t hi, lo;
        split2(o[nt][0] * inv0, o[nt][1] * inv0, hi, lo);
        g_Phi[row0 * 1024 + wd] = hi;
        g_Plo[row0 * 1024 + wd] = lo;
        split2(o[nt][2] * inv1, o[nt][3] * inv1, hi, lo);
        g_Phi[(row0 + 8) * 1024 + wd] = hi;
        g_Plo[(row0 + 8) * 1024 + wd] = lo;
    }
}

// ---------------- kernel_launch ---------------------------------------------
extern "C" void kernel_launch(void* const* d_in, const int* in_sizes, int n_in,
                              void* d_out, int out_size)
{
    const float* hidden = (const float*)d_in[0];
    const int*   pos    = (const int*)d_in[1];
    const float* Wqkv   = (const float*)d_in[2];
    const float* bqkv   = (const float*)d_in[3];
    const float* Wd     = (const float*)d_in[4];
    const float* bd     = (const float*)d_in[5];
    float* out = (float*)d_out;

    uint32_t *Ahi, *Alo, *Phi, *Plo;
    __nv_bfloat16 *Whi, *Wlo, *Dhi, *Dlo;
    cudaGetSymbolAddress((void**)&Ahi, g_Ahi);
    cudaGetSymbolAddress((void**)&Alo, g_Alo);
    cudaGetSymbolAddress((void**)&Whi, g_Whi);
    cudaGetSymbolAddress((void**)&Wlo, g_Wlo);
    cudaGetSymbolAddress((void**)&Dhi, g_DHhi);
    cudaGetSymbolAddress((void**)&Dlo, g_DHlo);
    cudaGetSymbolAddress((void**)&Phi, g_Phi);
    cudaGetSymbolAddress((void**)&Plo, g_Plo);

    cudaFuncSetAttribute(gemm_mma, cudaFuncAttributeMaxDynamicSharedMemorySize, GEMM_SMEM);
    cudaFuncSetAttribute(flash_mma, cudaFuncAttributeMaxDynamicSharedMemorySize, FA_SMEM);

    const int n4 = (M_ROWS * D_MODEL) / 4;

    split_convert<<<(n4 + 255) / 256, 256>>>(hidden, Ahi, Alo, n4);
    transpose_split<<<dim3(N_QKV / 32, D_MODEL / 32), dim3(32, 8)>>>(
        Wqkv, Whi, Wlo, D_MODEL, N_QKV);
    transpose_split<<<dim3(D_MODEL / 32, D_MODEL / 32), dim3(32, 8)>>>(
        Wd, Dhi, Dlo, D_MODEL, D_MODEL);
    rope_table<<<(S_LEN * 16 + 255) / 256, 256>>>();

    // QKV projection with fused RoPE/split/V-transpose epilogue
    gemm_mma<<<dim3(N_QKV / 128, M_ROWS / 128), 256, GEMM_SMEM>>>(
        Ahi, Alo, (const uint32_t*)Whi, (const uint32_t*)Wlo,
        bqkv, nullptr, pos, 1, M_ROWS, N_QKV, D_MODEL);

    flash_mma<<<dim3(S_LEN / 128, H, B_SZ), 256, FA_SMEM>>>();

    // Dense projection (plain epilogue -> d_out)
    gemm_mma<<<dim3(D_MODEL / 128, M_ROWS / 128), 256, GEMM_SMEM>>>(
        Phi, Plo, (const uint32_t*)Dhi, (const uint32_t*)Dlo,
        bd, out, pos, 0, M_ROWS, D_MODEL, D_MODEL);
}

// round 6
// speedup vs baseline: 1.0239x; 1.0239x over previous
#include <cuda_runtime.h>
#include <cuda_bf16.h>
#include <math.h>
#include <stdint.h>

#define H 16
#define HS 128
#define ROT 32
#define S_LEN 2048
#define B_SZ 2
#define D_MODEL 2048
#define N_QKV 6144
#define M_ROWS 4096
#define SCALE 0.08838834764831845f  // 1/sqrt(128)

// ---------------- scratch (__device__ globals) ------------------------------
__device__ float g_qkv[(size_t)M_ROWS * N_QKV];
__device__ uint32_t g_Ahi[(size_t)M_ROWS * D_MODEL / 2];
__device__ uint32_t g_Alo[(size_t)M_ROWS * D_MODEL / 2];
__device__ __nv_bfloat16 g_Whi[(size_t)N_QKV * D_MODEL];
__device__ __nv_bfloat16 g_Wlo[(size_t)N_QKV * D_MODEL];
__device__ __nv_bfloat16 g_DHhi[(size_t)D_MODEL * D_MODEL];
__device__ __nv_bfloat16 g_DHlo[(size_t)D_MODEL * D_MODEL];
__device__ uint32_t g_Phi[(size_t)M_ROWS * D_MODEL / 2];
__device__ uint32_t g_Plo[(size_t)M_ROWS * D_MODEL / 2];
__device__ uint32_t g_Qh[(size_t)B_SZ * H * S_LEN * (HS / 2)];
__device__ uint32_t g_Ql[(size_t)B_SZ * H * S_LEN * (HS / 2)];
__device__ uint32_t g_Kh[(size_t)B_SZ * H * S_LEN * (HS / 2)];
__device__ uint32_t g_Kl[(size_t)B_SZ * H * S_LEN * (HS / 2)];
__device__ uint32_t g_Vh[(size_t)B_SZ * H * HS * (S_LEN / 2)];
__device__ uint32_t g_Vl[(size_t)B_SZ * H * HS * (S_LEN / 2)];
__device__ float g_cosT[S_LEN * 16];
__device__ float g_sinT[S_LEN * 16];

// ---------------- PTX helpers ------------------------------------------------
__device__ __forceinline__ uint32_t smem_u32(const void* p) {
    uint32_t a;
    asm("{ .reg .u64 t; cvta.to.shared.u64 t, %1; cvt.u32.u64 %0, t; }"
        : "=r"(a) : "l"(p));
    return a;
}
__device__ __forceinline__ void cp16(uint32_t dst, const void* src) {
    asm volatile("cp.async.cg.shared.global [%0], [%1], 16;" :: "r"(dst), "l"(src));
}
__device__ __forceinline__ void cp_commit() {
    asm volatile("cp.async.commit_group;" ::: "memory");
}
template <int N>
__device__ __forceinline__ void cp_wait() {
    asm volatile("cp.async.wait_group %0;" :: "n"(N) : "memory");
}
__device__ __forceinline__ void ldm4(uint32_t* d, uint32_t addr) {
    asm volatile("ldmatrix.sync.aligned.m8n8.x4.shared.b16 {%0,%1,%2,%3}, [%4];"
                 : "=r"(d[0]), "=r"(d[1]), "=r"(d[2]), "=r"(d[3]) : "r"(addr));
}
__device__ __forceinline__ void mma16816(float* c, const uint32_t* a, const uint32_t* b)
{
    asm volatile(
        "mma.sync.aligned.m16n8k16.row.col.f32.bf16.bf16.f32 "
        "{%0,%1,%2,%3}, {%4,%5,%6,%7}, {%8,%9}, {%0,%1,%2,%3};"
        : "+f"(c[0]), "+f"(c[1]), "+f"(c[2]), "+f"(c[3])
        : "r"(a[0]), "r"(a[1]), "r"(a[2]), "r"(a[3]), "r"(b[0]), "r"(b[1]));
}
__device__ __forceinline__ void split2(float x, float y, uint32_t& hi, uint32_t& lo)
{
    __nv_bfloat162 h = __floats2bfloat162_rn(x, y);
    float rx = x - __bfloat162float(h.x);
    float ry = y - __bfloat162float(h.y);
    __nv_bfloat162 l = __floats2bfloat162_rn(rx, ry);
    hi = *reinterpret_cast<uint32_t*>(&h);
    lo = *reinterpret_cast<uint32_t*>(&l);
}

// ---------------- small prep kernels -----------------------------------------
__global__ void split_convert(const float* __restrict__ x,
                              uint32_t* __restrict__ hi,
                              uint32_t* __restrict__ lo, int n4)
{
    int i = blockIdx.x * blockDim.x + threadIdx.x;
    if (i >= n4) return;
    float4 v = ((const float4*)x)[i];
    uint32_t h0, l0, h1, l1;
    split2(v.x, v.y, h0, l0);
    split2(v.z, v.w, h1, l1);
    hi[i * 2]     = h0;
    hi[i * 2 + 1] = h1;
    lo[i * 2]     = l0;
    lo[i * 2 + 1] = l1;
}

__global__ void transpose_split(const float* __restrict__ W,
                                __nv_bfloat16* __restrict__ Thi,
                                __nv_bfloat16* __restrict__ Tlo, int K, int N)
{
    __shared__ float t[32][33];
    int n0 = blockIdx.x * 32, k0 = blockIdx.y * 32;
    int tx = threadIdx.x, ty = threadIdx.y;
#pragma unroll
    for (int i = 0; i < 32; i += 8)
        t[ty + i][tx] = W[(size_t)(k0 + ty + i) * N + n0 + tx];
    __syncthreads();
#pragma unroll
    for (int i = 0; i < 32; i += 8) {
        float x = t[tx][ty + i];
        __nv_bfloat16 h = __float2bfloat16_rn(x);
        __nv_bfloat16 l = __float2bfloat16_rn(x - __bfloat162float(h));
        size_t o = (size_t)(n0 + ty + i) * K + k0 + tx;
        Thi[o] = h;
        Tlo[o] = l;
    }
}

__global__ void rope_table()
{
    int idx = blockIdx.x * blockDim.x + threadIdx.x;
    if (idx >= S_LEN * 16) return;
    int p = idx >> 4, i = idx & 15;
    float inv = (float)pow(10000.0, -(double)(2 * i) / (double)ROT);
    float a = (float)p * inv;
    float s, c;
    sincosf(a, &s, &c);
    g_cosT[idx] = c;
    g_sinT[idx] = s;
}

// ---------------- qk_conv with fused RoPE ------------------------------------
__global__ void qk_conv(const int* __restrict__ pos)
{
    int idx = blockIdx.x * blockDim.x + threadIdx.x;  // M_ROWS*H*64
    int j = idx & 63;
    int h = (idx >> 6) & 15;
    int r = idx >> 10;
    const float* src = g_qkv + (size_t)r * N_QKV + h * (3 * HS);
    float q0, q1, k0, k1;

    if (j < 16) {
        int p = pos[r];
        const float* ct = g_cosT + p * 16;
        const float* st = g_sinT + p * 16;
        if (j < 8) {
            int d0 = 2 * j, d1 = 2 * j + 1;
            float c0 = ct[d0], s0 = st[d0], c1 = ct[d1], s1 = st[d1];
            q0 = src[d0] * c0 - src[d0 + 16] * s0;
            q1 = src[d1] * c1 - src[d1 + 16] * s1;
            k0 = src[HS + d0] * c0 - src[HS + d0 + 16] * s0;
            k1 = src[HS + d1] * c1 - src[HS + d1 + 16] * s1;
        } else {
            int d0 = 2 * j, d1 = 2 * j + 1;
            int i0 = d0 - 16, i1 = d1 - 16;
            float c0 = ct[i0], s0 = st[i0], c1 = ct[i1], s1 = st[i1];
            q0 = src[d0] * c0 + src[i0] * s0;
            q1 = src[d1] * c1 + src[i1] * s1;
            k0 = src[HS + d0] * c0 + src[HS + i0] * s0;
            k1 = src[HS + d1] * c1 + src[HS + i1] * s1;
        }
    } else {
        float2 q = *(const float2*)(src + 2 * j);
        float2 k = *(const float2*)(src + HS + 2 * j);
        q0 = q.x; q1 = q.y; k0 = k.x; k1 = k.y;
    }

    uint32_t qh, ql, kh, kl;
    split2(q0 * SCALE, q1 * SCALE, qh, ql);
    split2(k0, k1, kh, kl);
    int bh = (r >> 11) * H + h;
    size_t oi = ((size_t)bh * S_LEN + (r & 2047)) * 64 + j;
    g_Qh[oi] = qh;
    g_Ql[oi] = ql;
    g_Kh[oi] = kh;
    g_Kl[oi] = kl;
}

// ---------------- V transpose + split ----------------------------------------
__global__ __launch_bounds__(256) void v_conv()
{
    __shared__ float ts[64 * 133];
    const int s0 = blockIdx.x * 64;
    const int h  = blockIdx.y;
    const int b  = blockIdx.z;
    const int tid = threadIdx.x;

#pragma unroll
    for (int it = 0; it < 8; it++) {
        int f = tid + it * 256;
        int row = f >> 5, c4 = f & 31;
        float4 v = *(const float4*)(g_qkv + (size_t)(b * S_LEN + s0 + row) * N_QKV
                                    + h * (3 * HS) + 2 * HS + c4 * 4);
        ts[row * 133 + c4 * 4 + 0] = v.x;
        ts[row * 133 + c4 * 4 + 1] = v.y;
        ts[row * 133 + c4 * 4 + 2] = v.z;
        ts[row * 133 + c4 * 4 + 3] = v.w;
    }
    __syncthreads();

    const size_t obase = (size_t)(b * H + h) * HS * (S_LEN / 2);
#pragma unroll
    for (int it = 0; it < 16; it++) {
        int o = tid + it * 256;
        int d = o >> 5, j = o & 31;
        float v0 = ts[(2 * j) * 133 + d];
        float v1 = ts[(2 * j + 1) * 133 + d];
        uint32_t vh, vl;
        split2(v0, v1, vh, vl);
        size_t oi = obase + (size_t)d * (S_LEN / 2) + (s0 >> 1) + j;
        g_Vh[oi] = vh;
        g_Vl[oi] = vl;
    }
}

// ---------------- GEMM v2: 512 threads, 128x256 tile, 4-stage cp.async -------
// C[M,N] = A @ B^T + bias. 16 warps (4x4), warp tile 32x64, KC=32.
// Stage 48KB: Ah@0 (8K), Al@8K, Bh@16K (16K), Bl@32K. Row = 64B = 4 x 16B.
#define GKC 32
#define GSTG 49152
#define GEMM_SMEM (4 * GSTG)   // 192 KB

__device__ __forceinline__ uint32_t gswz(int row, int chunk) {
    return (uint32_t)(row * 64 + ((chunk ^ ((row >> 1) & 3)) << 4));
}

__global__ __launch_bounds__(512, 1) void gemm_mma(
    const uint32_t* __restrict__ Ah, const uint32_t* __restrict__ Al,
    const uint32_t* __restrict__ Bh, const uint32_t* __restrict__ Bl,
    const float* __restrict__ bias, float* __restrict__ C,
    int M, int N, int K)
{
    extern __shared__ uint32_t smg[];
    const uint32_t sb = smem_u32(smg);
    const int tid = threadIdx.x;
    const int w = tid >> 5, lane = tid & 31;
    const int g = lane >> 2, tig = lane & 3;
    const int r8 = lane & 7, mi = lane >> 3;
    const int wm = (w >> 2) * 32, wn = (w & 3) * 64;
    const int m0 = blockIdx.y * 128, n0 = blockIdx.x * 256;
    const int K2 = K >> 1;
    const int NCH = K / GKC;

    float acc[2][8][4];
#pragma unroll
    for (int i = 0; i < 2; i++)
#pragma unroll
        for (int j = 0; j < 8; j++)
#pragma unroll
            for (int k = 0; k < 4; k++) acc[i][j][k] = 0.0f;

    auto issue = [&](int c) {
        uint32_t st = sb + (c & 3) * GSTG;
        int kw = c * 16;
#pragma unroll
        for (int i = 0; i < 6; i++) {
            int idx = tid + i * 512;          // 3072 chunks total
            const uint32_t* gp;
            uint32_t dst;
            if (idx < 1024) {                 // A: hi then lo, 512 each
                int arr = idx >> 9, rem = idx & 511;
                int row = rem >> 2, ch = rem & 3;
                gp = (arr ? Al : Ah) + (size_t)(m0 + row) * K2 + kw + ch * 4;
                dst = st + arr * 8192 + gswz(row, ch);
            } else {                          // B: hi then lo, 1024 each
                int rem2 = idx - 1024;
                int arr = rem2 >> 10, rem = rem2 & 1023;
                int row = rem >> 2, ch = rem & 3;
                gp = (arr ? Bl : Bh) + (size_t)(n0 + row) * K2 + kw + ch * 4;
                dst = st + 16384 + arr * 16384 + gswz(row, ch);
            }
            cp16(dst, gp);
        }
        cp_commit();
    };

    issue(0); issue(1); issue(2);

    for (int c = 0; c < NCH; c++) {
        if (c + 3 < NCH) { issue(c + 3); cp_wait<3>(); }
        else             { cp_wait<0>(); }
        __syncthreads();
        uint32_t st = sb + (c & 3) * GSTG;

#pragma unroll
        for (int ks = 0; ks < 2; ks++) {
            // A fragments: 2 m-tiles (rows wm..wm+31)
            uint32_t ahf[2][4], alf[2][4];
#pragma unroll
            for (int mt = 0; mt < 2; mt++) {
                int row = wm + 16 * mt + ((mi & 1) << 3) + r8;
                int ch = 2 * ks + (mi >> 1);
                uint32_t sw = gswz(row, ch);
                ldm4(ahf[mt], st + sw);
                ldm4(alf[mt], st + 8192 + sw);
            }
            // B fragments in 2 halves of 4 n8-frags to bound registers
#pragma unroll
            for (int half = 0; half < 2; half++) {
                uint32_t bhf[4][2], blf[4][2];
#pragma unroll
                for (int j = 0; j < 2; j++) {
                    int row = wn + 32 * half + 16 * j + ((mi >> 1) << 3) + r8;
                    int ch = 2 * ks + (mi & 1);
                    uint32_t sw = gswz(row, ch);
                    uint32_t t4[4];
                    ldm4(t4, st + 16384 + sw);
                    bhf[2 * j][0] = t4[0]; bhf[2 * j][1] = t4[1];
                    bhf[2 * j + 1][0] = t4[2]; bhf[2 * j + 1][1] = t4[3];
                    ldm4(t4, st + 32768 + sw);
                    blf[2 * j][0] = t4[0]; blf[2 * j][1] = t4[1];
                    blf[2 * j + 1][0] = t4[2]; blf[2 * j + 1][1] = t4[3];
                }
#pragma unroll
                for (int mt = 0; mt < 2; mt++)
#pragma unroll
                    for (int nt = 0; nt < 4; nt++) {
                        float* a4 = acc[mt][4 * half + nt];
                        mma16816(a4, ahf[mt], bhf[nt]);
                        mma16816(a4, ahf[mt], blf[nt]);
                        mma16816(a4, alf[mt], bhf[nt]);
                    }
            }
        }
        __syncthreads();
    }

    // ---- epilogue: bias + fp32 store ----
#pragma unroll
    for (int mt = 0; mt < 2; mt++)
#pragma unroll
        for (int nt = 0; nt < 8; nt++) {
            int row = m0 + wm + 16 * mt + g;
            int col = n0 + wn + 8 * nt + 2 * tig;
            float2 bv = *(const float2*)(bias + col);
            float2 o0 = make_float2(acc[mt][nt][0] + bv.x, acc[mt][nt][1] + bv.y);
            float2 o1 = make_float2(acc[mt][nt][2] + bv.x, acc[mt][nt][3] + bv.y);
            *(float2*)&C[(size_t)row * N + col]       = o0;
            *(float2*)&C[(size_t)(row + 8) * N + col] = o1;
        }
}

// ---------------- flash attention: cp.async 2-stage + ldmatrix ---------------
#define FSTG 65536
#define FA_SMEM (2 * FSTG)

__device__ __forceinline__ uint32_t kswz(int row, int chunk) {
    return (uint32_t)(row * 256 + ((chunk ^ (row & 7)) << 4));
}
__device__ __forceinline__ uint32_t vswz(int row, int chunk) {
    return (uint32_t)(row * 128 + ((chunk ^ (row & 7)) << 4));
}

__global__ __launch_bounds__(256, 1) void flash_mma()
{
    extern __shared__ uint32_t smf[];
    const uint32_t sb = smem_u32(smf);

    const int qt = blockIdx.x, h = blockIdx.y, b = blockIdx.z;
    const int tid = threadIdx.x;
    const int w = tid >> 5, lane = tid & 31;
    const int g = lane >> 2, tig = lane & 3;
    const int r8 = lane & 7, mi = lane >> 3;
    const int bh = b * H + h;

    const size_t qrow = (size_t)bh * S_LEN + qt * 128 + w * 16;
    const uint32_t* q0h = g_Qh + (qrow + g) * 64;
    const uint32_t* q8h = q0h + 8 * 64;
    const uint32_t* q0l = g_Ql + (qrow + g) * 64;
    const uint32_t* q8l = q0l + 8 * 64;
    uint32_t qh[8][4], ql[8][4];
#pragma unroll
    for (int ds = 0; ds < 8; ds++) {
        qh[ds][0] = q0h[ds * 8 + tig];
        qh[ds][1] = q8h[ds * 8 + tig];
        qh[ds][2] = q0h[ds * 8 + 4 + tig];
        qh[ds][3] = q8h[ds * 8 + 4 + tig];
        ql[ds][0] = q0l[ds * 8 + tig];
        ql[ds][1] = q8l[ds * 8 + tig];
        ql[ds][2] = q0l[ds * 8 + 4 + tig];
        ql[ds][3] = q8l[ds * 8 + 4 + tig];
    }

    auto issueKV = [&](int kt) {
        uint32_t st = sb + (kt & 1) * FSTG;
        const size_t kbase = ((size_t)bh * S_LEN + kt * 64) * 64;
        const size_t vbase = (size_t)bh * HS * (S_LEN / 2) + kt * 32;
#pragma unroll
        for (int i = 0; i < 8; i++) {
            int idx = tid + i * 256;
            int arr = idx >> 10, rem = idx & 1023;
            int row = rem >> 4, ch = rem & 15;
            const uint32_t* src = (arr ? g_Kl : g_Kh) + kbase + row * 64 + ch * 4;
            cp16(st + arr * 16384 + kswz(row, ch), src);
        }
#pragma unroll
        for (int i = 0; i < 8; i++) {
            int idx = tid + i * 256;
            int arr = idx >> 10, rem = idx & 1023;
            int row = rem >> 3, ch = rem & 7;
            const uint32_t* src = (arr ? g_Vl : g_Vh) + vbase
                                  + (size_t)row * (S_LEN / 2) + ch * 4;
            cp16(st + 32768 + arr * 16384 + vswz(row, ch), src);
        }
        cp_commit();
    };

    float o[16][4];
#pragma unroll
    for (int i = 0; i < 16; i++)
#pragma unroll
        for (int k = 0; k < 4; k++) o[i][k] = 0.0f;
    float m0 = -1e30f, m1 = -1e30f, l0 = 0.0f, l1 = 0.0f;

    issueKV(0);

    for (int kt = 0; kt < S_LEN / 64; kt++) {
        if (kt + 1 < S_LEN / 64) { issueKV(kt + 1); cp_wait<1>(); }
        else                     { cp_wait<0>(); }
        __syncthreads();
        uint32_t st = sb + (kt & 1) * FSTG;

        float sc[8][4];
#pragma unroll
        for (int i = 0; i < 8; i++)
#pragma unroll
            for (int k = 0; k < 4; k++) sc[i][k] = 0.0f;

#pragma unroll
        for (int ds = 0; ds < 8; ds++) {
#pragma unroll
            for (int j = 0; j < 4; j++) {
                int row = 16 * j + ((mi >> 1) << 3) + r8;
                int ch = 2 * ds + (mi & 1);
                uint32_t sw = kswz(row, ch);
                uint32_t kh4[4], kl4[4];
                ldm4(kh4, st + sw);
                ldm4(kl4, st + 16384 + sw);
                mma16816(sc[2 * j],     qh[ds], kh4);
                mma16816(sc[2 * j],     qh[ds], kl4);
                mma16816(sc[2 * j],     ql[ds], kh4);
                mma16816(sc[2 * j + 1], qh[ds], kh4 + 2);
                mma16816(sc[2 * j + 1], qh[ds], kl4 + 2);
                mma16816(sc[2 * j + 1], ql[ds], kh4 + 2);
            }
        }

        float mx0 = -1e30f, mx1 = -1e30f;
#pragma unroll
        for (int nt = 0; nt < 8; nt++) {
            mx0 = fmaxf(mx0, fmaxf(sc[nt][0], sc[nt][1]));
            mx1 = fmaxf(mx1, fmaxf(sc[nt][2], sc[nt][3]));
        }
        mx0 = fmaxf(mx0, __shfl_xor_sync(0xffffffffu, mx0, 1));
        mx0 = fmaxf(mx0, __shfl_xor_sync(0xffffffffu, mx0, 2));
        mx1 = fmaxf(mx1, __shfl_xor_sync(0xffffffffu, mx1, 1));
        mx1 = fmaxf(mx1, __shfl_xor_sync(0xffffffffu, mx1, 2));

        float mn0 = fmaxf(m0, mx0);
        float mn1 = fmaxf(m1, mx1);
        float a0 = __expf(m0 - mn0);
        float a1 = __expf(m1 - mn1);
        m0 = mn0;
        m1 = mn1;
        float add0 = 0.0f, add1 = 0.0f;
#pragma unroll
        for (int nt = 0; nt < 8; nt++) {
            sc[nt][0] = __expf(sc[nt][0] - mn0);
            sc[nt][1] = __expf(sc[nt][1] - mn0);
            sc[nt][2] = __expf(sc[nt][2] - mn1);
            sc[nt][3] = __expf(sc[nt][3] - mn1);
            add0 += sc[nt][0] + sc[nt][1];
            add1 += sc[nt][2] + sc[nt][3];
        }
        l0 = l0 * a0 + add0;
        l1 = l1 * a1 + add1;
#pragma unroll
        for (int nt = 0; nt < 16; nt++) {
            o[nt][0] *= a0;
            o[nt][1] *= a0;
            o[nt][2] *= a1;
            o[nt][3] *= a1;
        }

#pragma unroll
        for (int kk = 0; kk < 4; kk++) {
            uint32_t ph[4], pl[4];
            split2(sc[2 * kk][0],     sc[2 * kk][1],     ph[0], pl[0]);
            split2(sc[2 * kk][2],     sc[2 * kk][3],     ph[1], pl[1]);
            split2(sc[2 * kk + 1][0], sc[2 * kk + 1][1], ph[2], pl[2]);
            split2(sc[2 * kk + 1][2], sc[2 * kk + 1][3], ph[3], pl[3]);
#pragma unroll
            for (int j = 0; j < 8; j++) {
                int row = 16 * j + ((mi >> 1) << 3) + r8;
                int ch = 2 * kk + (mi & 1);
                uint32_t sw = vswz(row, ch);
                uint32_t vh4[4], vl4[4];
                ldm4(vh4, st + 32768 + sw);
                ldm4(vl4, st + 49152 + sw);
                mma16816(o[2 * j],     ph, vh4);
                mma16816(o[2 * j],     ph, vl4);
                mma16816(o[2 * j],     pl, vh4);
                mma16816(o[2 * j + 1], ph, vh4 + 2);
                mma16816(o[2 * j + 1], ph, vl4 + 2);
                mma16816(o[2 * j + 1], pl, vh4 + 2);
            }
        }
        __syncthreads();
    }

    l0 += __shfl_xor_sync(0xffffffffu, l0, 1);
    l0 += __shfl_xor_sync(0xffffffffu, l0, 2);
    l1 += __shfl_xor_sync(0xffffffffu, l1, 1);
    l1 += __shfl_xor_sync(0xffffffffu, l1, 2);
    float inv0 = 1.0f / l0;
    float inv1 = 1.0f / l1;

    size_t row0 = (size_t)(b * S_LEN + qt * 128 + w * 16 + g);
#pragma unroll
    for (int nt = 0; nt < 16; nt++) {
        size_t wd = h * 64 + nt * 4 + tig;
        uint32_t hi, lo;
        split2(o[nt][0] * inv0, o[nt][1] * inv0, hi, lo);
        g_Phi[row0 * 1024 + wd] = hi;
        g_Plo[row0 * 1024 + wd] = lo;
        split2(o[nt][2] * inv1, o[nt][3] * inv1, hi, lo);
        g_Phi[(row0 + 8) * 1024 + wd] = hi;
        g_Plo[(row0 + 8) * 1024 + wd] = lo;
    }
}

// ---------------- kernel_launch ---------------------------------------------
extern "C" void kernel_launch(void* const* d_in, const int* in_sizes, int n_in,
                              void* d_out, int out_size)
{
    const float* hidden = (const float*)d_in[0];
    const int*   pos    = (const int*)d_in[1];
    const float* Wqkv   = (const float*)d_in[2];
    const float* bqkv   = (const float*)d_in[3];
    const float* Wd     = (const float*)d_in[4];
    const float* bd     = (const float*)d_in[5];
    float* out = (float*)d_out;

    float* qkv_p;
    uint32_t *Ahi, *Alo, *Phi, *Plo;
    __nv_bfloat16 *Whi, *Wlo, *Dhi, *Dlo;
    cudaGetSymbolAddress((void**)&qkv_p, g_qkv);
    cudaGetSymbolAddress((void**)&Ahi, g_Ahi);
    cudaGetSymbolAddress((void**)&Alo, g_Alo);
    cudaGetSymbolAddress((void**)&Whi, g_Whi);
    cudaGetSymbolAddress((void**)&Wlo, g_Wlo);
    cudaGetSymbolAddress((void**)&Dhi, g_DHhi);
    cudaGetSymbolAddress((void**)&Dlo, g_DHlo);
    cudaGetSymbolAddress((void**)&Phi, g_Phi);
    cudaGetSymbolAddress((void**)&Plo, g_Plo);

    cudaFuncSetAttribute(gemm_mma, cudaFuncAttributeMaxDynamicSharedMemorySize, GEMM_SMEM);
    cudaFuncSetAttribute(flash_mma, cudaFuncAttributeMaxDynamicSharedMemorySize, FA_SMEM);

    const int n4 = (M_ROWS * D_MODEL) / 4;

    split_convert<<<(n4 + 255) / 256, 256>>>(hidden, Ahi, Alo, n4);
    transpose_split<<<dim3(N_QKV / 32, D_MODEL / 32), dim3(32, 8)>>>(
        Wqkv, Whi, Wlo, D_MODEL, N_QKV);
    transpose_split<<<dim3(D_MODEL / 32, D_MODEL / 32), dim3(32, 8)>>>(
        Wd, Dhi, Dlo, D_MODEL, D_MODEL);
    rope_table<<<(S_LEN * 16 + 255) / 256, 256>>>();

    gemm_mma<<<dim3(N_QKV / 256, M_ROWS / 128), 512, GEMM_SMEM>>>(
        Ahi, Alo, (const uint32_t*)Whi, (const uint32_t*)Wlo,
        bqkv, qkv_p, M_ROWS, N_QKV, D_MODEL);

    qk_conv<<<(M_ROWS * H * 64) / 256, 256>>>(pos);
    v_conv<<<dim3(S_LEN / 64, H, B_SZ), 256>>>();

    flash_mma<<<dim3(S_LEN / 128, H, B_SZ), 256, FA_SMEM>>>();

    gemm_mma<<<dim3(D_MODEL / 256, M_ROWS / 128), 512, GEMM_SMEM>>>(
        Phi, Plo, (const uint32_t*)Dhi, (const uint32_t*)Dlo,
        bd, out, M_ROWS, D_MODEL, D_MODEL);
}

// round 7
// speedup vs baseline: 1.0329x; 1.0088x over previous
#include <cuda_runtime.h>
#include <cuda_bf16.h>
#include <math.h>
#include <stdint.h>

#define H 16
#define HS 128
#define ROT 32
#define S_LEN 2048
#define B_SZ 2
#define D_MODEL 2048
#define N_QKV 6144
#define M_ROWS 4096
#define SCALE 0.08838834764831845f  // 1/sqrt(128)

// ---------------- scratch (__device__ globals) ------------------------------
__device__ float g_qkv[(size_t)M_ROWS * N_QKV];
__device__ uint32_t g_Ahi[(size_t)M_ROWS * D_MODEL / 2];
__device__ uint32_t g_Alo[(size_t)M_ROWS * D_MODEL / 2];
__device__ __nv_bfloat16 g_Whi[(size_t)N_QKV * D_MODEL];
__device__ __nv_bfloat16 g_Wlo[(size_t)N_QKV * D_MODEL];
__device__ __nv_bfloat16 g_DHhi[(size_t)D_MODEL * D_MODEL];
__device__ __nv_bfloat16 g_DHlo[(size_t)D_MODEL * D_MODEL];
__device__ uint32_t g_Phi[(size_t)M_ROWS * D_MODEL / 2];
__device__ uint32_t g_Plo[(size_t)M_ROWS * D_MODEL / 2];
__device__ uint32_t g_Qh[(size_t)B_SZ * H * S_LEN * (HS / 2)];
__device__ uint32_t g_Ql[(size_t)B_SZ * H * S_LEN * (HS / 2)];
__device__ uint32_t g_Kh[(size_t)B_SZ * H * S_LEN * (HS / 2)];
__device__ uint32_t g_Kl[(size_t)B_SZ * H * S_LEN * (HS / 2)];
__device__ uint32_t g_Vh[(size_t)B_SZ * H * HS * (S_LEN / 2)];
__device__ uint32_t g_Vl[(size_t)B_SZ * H * HS * (S_LEN / 2)];
__device__ float g_cosT[S_LEN * 16];
__device__ float g_sinT[S_LEN * 16];

// ---------------- PTX helpers ------------------------------------------------
__device__ __forceinline__ uint32_t smem_u32(const void* p) {
    uint32_t a;
    asm("{ .reg .u64 t; cvta.to.shared.u64 t, %1; cvt.u32.u64 %0, t; }"
        : "=r"(a) : "l"(p));
    return a;
}
__device__ __forceinline__ void cp16(uint32_t dst, const void* src) {
    asm volatile("cp.async.cg.shared.global [%0], [%1], 16;" :: "r"(dst), "l"(src));
}
__device__ __forceinline__ void cp_commit() {
    asm volatile("cp.async.commit_group;" ::: "memory");
}
template <int N>
__device__ __forceinline__ void cp_wait() {
    asm volatile("cp.async.wait_group %0;" :: "n"(N) : "memory");
}
__device__ __forceinline__ void ldm4(uint32_t* d, uint32_t addr) {
    asm volatile("ldmatrix.sync.aligned.m8n8.x4.shared.b16 {%0,%1,%2,%3}, [%4];"
                 : "=r"(d[0]), "=r"(d[1]), "=r"(d[2]), "=r"(d[3]) : "r"(addr));
}
__device__ __forceinline__ void mma16816(float* c, const uint32_t* a, const uint32_t* b)
{
    asm volatile(
        "mma.sync.aligned.m16n8k16.row.col.f32.bf16.bf16.f32 "
        "{%0,%1,%2,%3}, {%4,%5,%6,%7}, {%8,%9}, {%0,%1,%2,%3};"
        : "+f"(c[0]), "+f"(c[1]), "+f"(c[2]), "+f"(c[3])
        : "r"(a[0]), "r"(a[1]), "r"(a[2]), "r"(a[3]), "r"(b[0]), "r"(b[1]));
}
__device__ __forceinline__ void split2(float x, float y, uint32_t& hi, uint32_t& lo)
{
    __nv_bfloat162 h = __floats2bfloat162_rn(x, y);
    float rx = x - __bfloat162float(h.x);
    float ry = y - __bfloat162float(h.y);
    __nv_bfloat162 l = __floats2bfloat162_rn(rx, ry);
    hi = *reinterpret_cast<uint32_t*>(&h);
    lo = *reinterpret_cast<uint32_t*>(&l);
}

// ---------------- small prep kernels -----------------------------------------
__global__ void split_convert(const float* __restrict__ x,
                              uint32_t* __restrict__ hi,
                              uint32_t* __restrict__ lo, int n4)
{
    int i = blockIdx.x * blockDim.x + threadIdx.x;
    if (i >= n4) return;
    float4 v = ((const float4*)x)[i];
    uint32_t h0, l0, h1, l1;
    split2(v.x, v.y, h0, l0);
    split2(v.z, v.w, h1, l1);
    hi[i * 2]     = h0;
    hi[i * 2 + 1] = h1;
    lo[i * 2]     = l0;
    lo[i * 2 + 1] = l1;
}

__global__ void transpose_split(const float* __restrict__ W,
                                __nv_bfloat16* __restrict__ Thi,
                                __nv_bfloat16* __restrict__ Tlo, int K, int N)
{
    __shared__ float t[32][33];
    int n0 = blockIdx.x * 32, k0 = blockIdx.y * 32;
    int tx = threadIdx.x, ty = threadIdx.y;
#pragma unroll
    for (int i = 0; i < 32; i += 8)
        t[ty + i][tx] = W[(size_t)(k0 + ty + i) * N + n0 + tx];
    __syncthreads();
#pragma unroll
    for (int i = 0; i < 32; i += 8) {
        float x = t[tx][ty + i];
        __nv_bfloat16 h = __float2bfloat16_rn(x);
        __nv_bfloat16 l = __float2bfloat16_rn(x - __bfloat162float(h));
        size_t o = (size_t)(n0 + ty + i) * K + k0 + tx;
        Thi[o] = h;
        Tlo[o] = l;
    }
}

__global__ void rope_table()
{
    int idx = blockIdx.x * blockDim.x + threadIdx.x;
    if (idx >= S_LEN * 16) return;
    int p = idx >> 4, i = idx & 15;
    float inv = (float)pow(10000.0, -(double)(2 * i) / (double)ROT);
    float a = (float)p * inv;
    float s, c;
    sincosf(a, &s, &c);
    g_cosT[idx] = c;
    g_sinT[idx] = s;
}

// ---------------- qk_conv with fused RoPE ------------------------------------
__global__ void qk_conv(const int* __restrict__ pos)
{
    int idx = blockIdx.x * blockDim.x + threadIdx.x;  // M_ROWS*H*64
    int j = idx & 63;
    int h = (idx >> 6) & 15;
    int r = idx >> 10;
    const float* src = g_qkv + (size_t)r * N_QKV + h * (3 * HS);
    float q0, q1, k0, k1;

    if (j < 16) {
        int p = pos[r];
        const float* ct = g_cosT + p * 16;
        const float* st = g_sinT + p * 16;
        if (j < 8) {
            int d0 = 2 * j, d1 = 2 * j + 1;
            float c0 = ct[d0], s0 = st[d0], c1 = ct[d1], s1 = st[d1];
            q0 = src[d0] * c0 - src[d0 + 16] * s0;
            q1 = src[d1] * c1 - src[d1 + 16] * s1;
            k0 = src[HS + d0] * c0 - src[HS + d0 + 16] * s0;
            k1 = src[HS + d1] * c1 - src[HS + d1 + 16] * s1;
        } else {
            int d0 = 2 * j, d1 = 2 * j + 1;
            int i0 = d0 - 16, i1 = d1 - 16;
            float c0 = ct[i0], s0 = st[i0], c1 = ct[i1], s1 = st[i1];
            q0 = src[d0] * c0 + src[i0] * s0;
            q1 = src[d1] * c1 + src[i1] * s1;
            k0 = src[HS + d0] * c0 + src[HS + i0] * s0;
            k1 = src[HS + d1] * c1 + src[HS + i1] * s1;
        }
    } else {
        float2 q = *(const float2*)(src + 2 * j);
        float2 k = *(const float2*)(src + HS + 2 * j);
        q0 = q.x; q1 = q.y; k0 = k.x; k1 = k.y;
    }

    uint32_t qh, ql, kh, kl;
    split2(q0 * SCALE, q1 * SCALE, qh, ql);
    split2(k0, k1, kh, kl);
    int bh = (r >> 11) * H + h;
    size_t oi = ((size_t)bh * S_LEN + (r & 2047)) * 64 + j;
    g_Qh[oi] = qh;
    g_Ql[oi] = ql;
    g_Kh[oi] = kh;
    g_Kl[oi] = kl;
}

// ---------------- V transpose + split ----------------------------------------
__global__ __launch_bounds__(256) void v_conv()
{
    __shared__ float ts[64 * 133];
    const int s0 = blockIdx.x * 64;
    const int h  = blockIdx.y;
    const int b  = blockIdx.z;
    const int tid = threadIdx.x;

#pragma unroll
    for (int it = 0; it < 8; it++) {
        int f = tid + it * 256;
        int row = f >> 5, c4 = f & 31;
        float4 v = *(const float4*)(g_qkv + (size_t)(b * S_LEN + s0 + row) * N_QKV
                                    + h * (3 * HS) + 2 * HS + c4 * 4);
        ts[row * 133 + c4 * 4 + 0] = v.x;
        ts[row * 133 + c4 * 4 + 1] = v.y;
        ts[row * 133 + c4 * 4 + 2] = v.z;
        ts[row * 133 + c4 * 4 + 3] = v.w;
    }
    __syncthreads();

    const size_t obase = (size_t)(b * H + h) * HS * (S_LEN / 2);
#pragma unroll
    for (int it = 0; it < 16; it++) {
        int o = tid + it * 256;
        int d = o >> 5, j = o & 31;
        float v0 = ts[(2 * j) * 133 + d];
        float v1 = ts[(2 * j + 1) * 133 + d];
        uint32_t vh, vl;
        split2(v0, v1, vh, vl);
        size_t oi = obase + (size_t)d * (S_LEN / 2) + (s0 >> 1) + j;
        g_Vh[oi] = vh;
        g_Vl[oi] = vl;
    }
}

// ---------------- GEMM: cp.async 4-stage + ldmatrix (one sync/chunk) ---------
// C[M,N] = A @ B^T + bias. Block 128x128, 8 warps (2x4), warp 64x32, KC=32.
// Stage 32KB: Ah@0, Al@8K, Bh@16K, Bl@24K. Row = 64B = 4 chunks of 16B.
#define GKC 32
#define GSTG 32768
#define GEMM_SMEM (4 * GSTG)

__device__ __forceinline__ uint32_t gswz(int row, int chunk) {
    return (uint32_t)(row * 64 + ((chunk ^ ((row >> 1) & 3)) << 4));
}

__global__ __launch_bounds__(256, 1) void gemm_mma(
    const uint32_t* __restrict__ Ah, const uint32_t* __restrict__ Al,
    const uint32_t* __restrict__ Bh, const uint32_t* __restrict__ Bl,
    const float* __restrict__ bias, float* __restrict__ C,
    int M, int N, int K)
{
    extern __shared__ uint32_t smg[];
    const uint32_t sb = smem_u32(smg);
    const int tid = threadIdx.x;
    const int w = tid >> 5, lane = tid & 31;
    const int g = lane >> 2, tig = lane & 3;
    const int r8 = lane & 7, mi = lane >> 3;
    const int wm = (w >> 2) * 64, wn = (w & 3) * 32;
    const int m0 = blockIdx.y * 128, n0 = blockIdx.x * 128;
    const int K2 = K >> 1;
    const int NCH = K / GKC;

    float acc[4][4][4];
#pragma unroll
    for (int i = 0; i < 4; i++)
#pragma unroll
        for (int j = 0; j < 4; j++)
#pragma unroll
            for (int k = 0; k < 4; k++) acc[i][j][k] = 0.0f;

    auto issue = [&](int c) {
        uint32_t st = sb + (c & 3) * GSTG;
        int kw = c * 16;
#pragma unroll
        for (int i = 0; i < 8; i++) {
            int idx = tid + i * 256;
            int arr = idx >> 9, rem = idx & 511;
            int row = rem >> 2, ch = rem & 3;
            const uint32_t* gp;
            if (arr == 0)      gp = Ah + (size_t)(m0 + row) * K2 + kw + ch * 4;
            else if (arr == 1) gp = Al + (size_t)(m0 + row) * K2 + kw + ch * 4;
            else if (arr == 2) gp = Bh + (size_t)(n0 + row) * K2 + kw + ch * 4;
            else               gp = Bl + (size_t)(n0 + row) * K2 + kw + ch * 4;
            cp16(st + arr * 8192 + gswz(row, ch), gp);
        }
        cp_commit();
    };

    issue(0); issue(1); issue(2);

    for (int c = 0; c < NCH; c++) {
        // oldest outstanding group = c; outstanding = min(3, NCH - c)
        if (c <= NCH - 3)      cp_wait<2>();
        else if (c == NCH - 2) cp_wait<1>();
        else                   cp_wait<0>();
        __syncthreads();                       // all warps done reading slot (c-1)%4
        if (c + 3 < NCH) issue(c + 3);         // writes slot (c-1)%4 — safe now
        uint32_t st = sb + (c & 3) * GSTG;

#pragma unroll
        for (int ks = 0; ks < 2; ks++) {
            uint32_t ahf[4][4], alf[4][4], bhf[4][2], blf[4][2];
#pragma unroll
            for (int mt = 0; mt < 4; mt++) {
                int row = wm + 16 * mt + ((mi & 1) << 3) + r8;
                int ch = 2 * ks + (mi >> 1);
                uint32_t sw = gswz(row, ch);
                ldm4(ahf[mt], st + sw);
                ldm4(alf[mt], st + 8192 + sw);
            }
#pragma unroll
            for (int j = 0; j < 2; j++) {
                int row = wn + 16 * j + ((mi >> 1) << 3) + r8;
                int ch = 2 * ks + (mi & 1);
                uint32_t sw = gswz(row, ch);
                uint32_t t4[4];
                ldm4(t4, st + 16384 + sw);
                bhf[2 * j][0] = t4[0]; bhf[2 * j][1] = t4[1];
                bhf[2 * j + 1][0] = t4[2]; bhf[2 * j + 1][1] = t4[3];
                ldm4(t4, st + 24576 + sw);
                blf[2 * j][0] = t4[0]; blf[2 * j][1] = t4[1];
                blf[2 * j + 1][0] = t4[2]; blf[2 * j + 1][1] = t4[3];
            }
#pragma unroll
            for (int mt = 0; mt < 4; mt++)
#pragma unroll
                for (int nt = 0; nt < 4; nt++) {
                    mma16816(acc[mt][nt], ahf[mt], bhf[nt]);
                    mma16816(acc[mt][nt], ahf[mt], blf[nt]);
                    mma16816(acc[mt][nt], alf[mt], bhf[nt]);
                }
        }
    }

#pragma unroll
    for (int mt = 0; mt < 4; mt++)
#pragma unroll
        for (int nt = 0; nt < 4; nt++) {
            int row = m0 + wm + 16 * mt + g;
            int col = n0 + wn + 8 * nt + 2 * tig;
            float2 bv = *(const float2*)(bias + col);
            float2 o0 = make_float2(acc[mt][nt][0] + bv.x, acc[mt][nt][1] + bv.y);
            float2 o1 = make_float2(acc[mt][nt][2] + bv.x, acc[mt][nt][3] + bv.y);
            *(float2*)&C[(size_t)row * N + col]       = o0;
            *(float2*)&C[(size_t)(row + 8) * N + col] = o1;
        }
}

// ---------------- flash attention: 3-buffer cp.async + ldmatrix --------------
// Block: BQ=128, 256 threads (8 warps x 16 rows). BK=64.
// Stage 64KB: Kh@0, Kl@16K, Vh@32K, Vl@48K. 3 buffers = 192KB.
#define FSTG 65536
#define FA_SMEM (3 * FSTG)

__device__ __forceinline__ uint32_t kswz(int row, int chunk) {
    return (uint32_t)(row * 256 + ((chunk ^ (row & 7)) << 4));
}
__device__ __forceinline__ uint32_t vswz(int row, int chunk) {
    return (uint32_t)(row * 128 + ((chunk ^ (row & 7)) << 4));
}

__global__ __launch_bounds__(256, 1) void flash_mma()
{
    extern __shared__ uint32_t smf[];
    const uint32_t sb = smem_u32(smf);

    const int qt = blockIdx.x, h = blockIdx.y, b = blockIdx.z;
    const int tid = threadIdx.x;
    const int w = tid >> 5, lane = tid & 31;
    const int g = lane >> 2, tig = lane & 3;
    const int r8 = lane & 7, mi = lane >> 3;
    const int bh = b * H + h;
    const int NT = S_LEN / 64;

    const size_t qrow = (size_t)bh * S_LEN + qt * 128 + w * 16;
    const uint32_t* q0h = g_Qh + (qrow + g) * 64;
    const uint32_t* q8h = q0h + 8 * 64;
    const uint32_t* q0l = g_Ql + (qrow + g) * 64;
    const uint32_t* q8l = q0l + 8 * 64;
    uint32_t qh[8][4], ql[8][4];
#pragma unroll
    for (int ds = 0; ds < 8; ds++) {
        qh[ds][0] = q0h[ds * 8 + tig];
        qh[ds][1] = q8h[ds * 8 + tig];
        qh[ds][2] = q0h[ds * 8 + 4 + tig];
        qh[ds][3] = q8h[ds * 8 + 4 + tig];
        ql[ds][0] = q0l[ds * 8 + tig];
        ql[ds][1] = q8l[ds * 8 + tig];
        ql[ds][2] = q0l[ds * 8 + 4 + tig];
        ql[ds][3] = q8l[ds * 8 + 4 + tig];
    }

    auto issueKV = [&](int kt) {
        uint32_t st = sb + (kt % 3) * FSTG;
        const size_t kbase = ((size_t)bh * S_LEN + kt * 64) * 64;
        const size_t vbase = (size_t)bh * HS * (S_LEN / 2) + kt * 32;
#pragma unroll
        for (int i = 0; i < 8; i++) {
            int idx = tid + i * 256;
            int arr = idx >> 10, rem = idx & 1023;
            int row = rem >> 4, ch = rem & 15;
            const uint32_t* src = (arr ? g_Kl : g_Kh) + kbase + row * 64 + ch * 4;
            cp16(st + arr * 16384 + kswz(row, ch), src);
        }
#pragma unroll
        for (int i = 0; i < 8; i++) {
            int idx = tid + i * 256;
            int arr = idx >> 10, rem = idx & 1023;
            int row = rem >> 3, ch = rem & 7;
            const uint32_t* src = (arr ? g_Vl : g_Vh) + vbase
                                  + (size_t)row * (S_LEN / 2) + ch * 4;
            cp16(st + 32768 + arr * 16384 + vswz(row, ch), src);
        }
        cp_commit();
    };

    float o[16][4];
#pragma unroll
    for (int i = 0; i < 16; i++)
#pragma unroll
        for (int k = 0; k < 4; k++) o[i][k] = 0.0f;
    float m0 = -1e30f, m1 = -1e30f, l0 = 0.0f, l1 = 0.0f;

    issueKV(0);
    issueKV(1);

    for (int kt = 0; kt < NT; kt++) {
        // oldest outstanding group = kt; outstanding = min(2, NT - kt)
        if (kt <= NT - 2) cp_wait<1>();
        else              cp_wait<0>();
        __syncthreads();                      // all warps done reading slot (kt-1)%3
        if (kt + 2 < NT) issueKV(kt + 2);     // writes slot (kt-1)%3 — safe now
        uint32_t st = sb + (kt % 3) * FSTG;

        float sc[8][4];
#pragma unroll
        for (int i = 0; i < 8; i++)
#pragma unroll
            for (int k = 0; k < 4; k++) sc[i][k] = 0.0f;

#pragma unroll
        for (int ds = 0; ds < 8; ds++) {
#pragma unroll
            for (int j = 0; j < 4; j++) {
                int row = 16 * j + ((mi >> 1) << 3) + r8;
                int ch = 2 * ds + (mi & 1);
                uint32_t sw = kswz(row, ch);
                uint32_t kh4[4], kl4[4];
                ldm4(kh4, st + sw);
                ldm4(kl4, st + 16384 + sw);
                mma16816(sc[2 * j],     qh[ds], kh4);
                mma16816(sc[2 * j],     qh[ds], kl4);
                mma16816(sc[2 * j],     ql[ds], kh4);
                mma16816(sc[2 * j + 1], qh[ds], kh4 + 2);
                mma16816(sc[2 * j + 1], qh[ds], kl4 + 2);
                mma16816(sc[2 * j + 1], ql[ds], kh4 + 2);
            }
        }

        float mx0 = -1e30f, mx1 = -1e30f;
#pragma unroll
        for (int nt = 0; nt < 8; nt++) {
            mx0 = fmaxf(mx0, fmaxf(sc[nt][0], sc[nt][1]));
            mx1 = fmaxf(mx1, fmaxf(sc[nt][2], sc[nt][3]));
        }
        mx0 = fmaxf(mx0, __shfl_xor_sync(0xffffffffu, mx0, 1));
        mx0 = fmaxf(mx0, __shfl_xor_sync(0xffffffffu, mx0, 2));
        mx1 = fmaxf(mx1, __shfl_xor_sync(0xffffffffu, mx1, 1));
        mx1 = fmaxf(mx1, __shfl_xor_sync(0xffffffffu, mx1, 2));

        float mn0 = fmaxf(m0, mx0);
        float mn1 = fmaxf(m1, mx1);
        float a0 = __expf(m0 - mn0);
        float a1 = __expf(m1 - mn1);
        m0 = mn0;
        m1 = mn1;
        float add0 = 0.0f, add1 = 0.0f;
#pragma unroll
        for (int nt = 0; nt < 8; nt++) {
            sc[nt][0] = __expf(sc[nt][0] - mn0);
            sc[nt][1] = __expf(sc[nt][1] - mn0);
            sc[nt][2] = __expf(sc[nt][2] - mn1);
            sc[nt][3] = __expf(sc[nt][3] - mn1);
            add0 += sc[nt][0] + sc[nt][1];
            add1 += sc[nt][2] + sc[nt][3];
        }
        l0 = l0 * a0 + add0;
        l1 = l1 * a1 + add1;
#pragma unroll
        for (int nt = 0; nt < 16; nt++) {
            o[nt][0] *= a0;
            o[nt][1] *= a0;
            o[nt][2] *= a1;
            o[nt][3] *= a1;
        }

#pragma unroll
        for (int kk = 0; kk < 4; kk++) {
            uint32_t ph[4], pl[4];
            split2(sc[2 * kk][0],     sc[2 * kk][1],     ph[0], pl[0]);
            split2(sc[2 * kk][2],     sc[2 * kk][3],     ph[1], pl[1]);
            split2(sc[2 * kk + 1][0], sc[2 * kk + 1][1], ph[2], pl[2]);
            split2(sc[2 * kk + 1][2], sc[2 * kk + 1][3], ph[3], pl[3]);
#pragma unroll
            for (int j = 0; j < 8; j++) {
                int row = 16 * j + ((mi >> 1) << 3) + r8;
                int ch = 2 * kk + (mi & 1);
                uint32_t sw = vswz(row, ch);
                uint32_t vh4[4], vl4[4];
                ldm4(vh4, st + 32768 + sw);
                ldm4(vl4, st + 49152 + sw);
                mma16816(o[2 * j],     ph, vh4);
                mma16816(o[2 * j],     ph, vl4);
                mma16816(o[2 * j],     pl, vh4);
                mma16816(o[2 * j + 1], ph, vh4 + 2);
                mma16816(o[2 * j + 1], ph, vl4 + 2);
                mma16816(o[2 * j + 1], pl, vh4 + 2);
            }
        }
    }

    l0 += __shfl_xor_sync(0xffffffffu, l0, 1);
    l0 += __shfl_xor_sync(0xffffffffu, l0, 2);
    l1 += __shfl_xor_sync(0xffffffffu, l1, 1);
    l1 += __shfl_xor_sync(0xffffffffu, l1, 2);
    float inv0 = 1.0f / l0;
    float inv1 = 1.0f / l1;

    size_t row0 = (size_t)(b * S_LEN + qt * 128 + w * 16 + g);
#pragma unroll
    for (int nt = 0; nt < 16; nt++) {
        size_t wd = h * 64 + nt * 4 + tig;
        uint32_t hi, lo;
        split2(o[nt][0] * inv0, o[nt][1] * inv0, hi, lo);
        g_Phi[row0 * 1024 + wd] = hi;
        g_Plo[row0 * 1024 + wd] = lo;
        split2(o[nt][2] * inv1, o[nt][3] * inv1, hi, lo);
        g_Phi[(row0 + 8) * 1024 + wd] = hi;
        g_Plo[(row0 + 8) * 1024 + wd] = lo;
    }
}

// ---------------- kernel_launch ---------------------------------------------
extern "C" void kernel_launch(void* const* d_in, const int* in_sizes, int n_in,
                              void* d_out, int out_size)
{
    const float* hidden = (const float*)d_in[0];
    const int*   pos    = (const int*)d_in[1];
    const float* Wqkv   = (const float*)d_in[2];
    const float* bqkv   = (const float*)d_in[3];
    const float* Wd     = (const float*)d_in[4];
    const float* bd     = (const float*)d_in[5];
    float* out = (float*)d_out;

    float* qkv_p;
    uint32_t *Ahi, *Alo, *Phi, *Plo;
    __nv_bfloat16 *Whi, *Wlo, *Dhi, *Dlo;
    cudaGetSymbolAddress((void**)&qkv_p, g_qkv);
    cudaGetSymbolAddress((void**)&Ahi, g_Ahi);
    cudaGetSymbolAddress((void**)&Alo, g_Alo);
    cudaGetSymbolAddress((void**)&Whi, g_Whi);
    cudaGetSymbolAddress((void**)&Wlo, g_Wlo);
    cudaGetSymbolAddress((void**)&Dhi, g_DHhi);
    cudaGetSymbolAddress((void**)&Dlo, g_DHlo);
    cudaGetSymbolAddress((void**)&Phi, g_Phi);
    cudaGetSymbolAddress((void**)&Plo, g_Plo);

    cudaFuncSetAttribute(gemm_mma, cudaFuncAttributeMaxDynamicSharedMemorySize, GEMM_SMEM);
    cudaFuncSetAttribute(flash_mma, cudaFuncAttributeMaxDynamicSharedMemorySize, FA_SMEM);

    const int n4 = (M_ROWS * D_MODEL) / 4;

    // launch order: QKV gemm is 4th so ncu's sampled slot lands on it
    split_convert<<<(n4 + 255) / 256, 256>>>(hidden, Ahi, Alo, n4);
    transpose_split<<<dim3(N_QKV / 32, D_MODEL / 32), dim3(32, 8)>>>(
        Wqkv, Whi, Wlo, D_MODEL, N_QKV);
    transpose_split<<<dim3(D_MODEL / 32, D_MODEL / 32), dim3(32, 8)>>>(
        Wd, Dhi, Dlo, D_MODEL, D_MODEL);

    gemm_mma<<<dim3(N_QKV / 128, M_ROWS / 128), 256, GEMM_SMEM>>>(
        Ahi, Alo, (const uint32_t*)Whi, (const uint32_t*)Wlo,
        bqkv, qkv_p, M_ROWS, N_QKV, D_MODEL);

    rope_table<<<(S_LEN * 16 + 255) / 256, 256>>>();
    qk_conv<<<(M_ROWS * H * 64) / 256, 256>>>(pos);
    v_conv<<<dim3(S_LEN / 64, H, B_SZ), 256>>>();

    flash_mma<<<dim3(S_LEN / 128, H, B_SZ), 256, FA_SMEM>>>();

    gemm_mma<<<dim3(D_MODEL / 128, M_ROWS / 128), 256, GEMM_SMEM>>>(
        Phi, Plo, (const uint32_t*)Dhi, (const uint32_t*)Dlo,
        bd, out, M_ROWS, D_MODEL, D_MODEL);
}